// round 15
// baseline (speedup 1.0000x reference)
#include <cuda_runtime.h>
#include <cuda_fp16.h>
#include <cuda_bf16.h>
#include <cfloat>
#include <cstdint>

// ResidualVectorQuantizer, exact argmin via bf16-MMA prefilter + scalar verify.
// B=16,E=64,H=64,W=64 -> N=65536 tokens; K=1024, NC=8 stages.
//
// Exact reference numerics (validated rel_err==0 in rounds 1-6, 8, 10, 13):
//   r2  = sequential sum of rounded squares of res (e ascending)
//   dot = sequential fused-FMA over e ascending
//   d   = fl(fl(r2 - fl(2*dot)) + cb2), argmin first-index tie-break
//   res -= q elementwise rounded; quant = ((q0+q1)+...)+q7
// MMA computes approximate scores t~ = cb2 - 2*dot~ (bf16 in, f32 acc,
// fp16-stored); every k with t~ <= min + MARGIN=2e-3 is re-verified exactly.
//
// R14 = R13 (716us best, profiled: L1 57%, no pipe saturated) + 3 edits:
//  1. per-token score min tracked in registers during the MMA epilogue
//     (hmin2 of the exact same fp16 values that get stored) + quad-shfl +
//     atomicMin(float-ordered uint) -> identical thr, identical candidates
//  2. scan drops its min pass entirely (pure threshold extraction)
//  3. select/residual-update are warp-local: post-select barrier -> shfl
//     broadcast of k; sel[] removed

#define NTOK   65536
#define EDIM   64
#define KCB    1024
#define NCODE  8
#define MTOK   64          // tokens per CTA
#define TPB    512
#define NWARP  16
#define GTW    128         // codebook k-gtile width (codewords)
#define NGT    (KCB / GTW) // 8 gtiles
#define BPITCH 136         // B tile pitch in 32-bit words (136%32==8)
#define BUFW   (32 * BPITCH)   // words per B buffer
#define RPITCH 68          // res row pitch (floats)
#define SCP    1032        // score row pitch (halves)
#define CAP    48
#define MARGIN 2e-3f

// packed bf16 pairs along e: word(e2,k) = {lo=cb[k][2e2], hi=cb[k][2e2+1]}
__device__ unsigned g_cbt[NCODE * (EDIM/2) * KCB];
__device__ float    g_cb2[NCODE * KCB];         // exact ||cb||^2

__device__ __forceinline__ unsigned packbf(float lo, float hi) {
    unsigned r;
    asm("cvt.rn.bf16x2.f32 %0, %1, %2;" : "=r"(r) : "f"(hi), "f"(lo));
    return r;
}

__device__ __forceinline__ __half2 u2h2(unsigned u) {
    return *reinterpret_cast<__half2*>(&u);
}

// float <-> order-preserving unsigned (for atomicMin on floats, no NaNs)
__device__ __forceinline__ unsigned fenc(float f) {
    unsigned u = __float_as_uint(f);
    return (u & 0x80000000u) ? ~u : (u | 0x80000000u);
}
__device__ __forceinline__ float fdec(unsigned e) {
    return (e & 0x80000000u) ? __uint_as_float(e ^ 0x80000000u)
                             : __uint_as_float(~e);
}

__device__ __forceinline__ void mma_bf16(float& c0, float& c1, float& c2, float& c3,
                                         unsigned a0, unsigned a1, unsigned a2, unsigned a3,
                                         unsigned b0, unsigned b1) {
    asm volatile(
        "mma.sync.aligned.m16n8k16.row.col.f32.bf16.bf16.f32 "
        "{%0,%1,%2,%3}, {%4,%5,%6,%7}, {%8,%9}, {%0,%1,%2,%3};\n"
        : "+f"(c0), "+f"(c1), "+f"(c2), "+f"(c3)
        : "r"(a0), "r"(a1), "r"(a2), "r"(a3), "r"(b0), "r"(b1));
}

// ---- precompute: exact cb2 + transposed bf16-packed codebook ----
__global__ void prep_kernel(const float* __restrict__ cb)
{
    const int i = blockIdx.x * blockDim.x + threadIdx.x;   // 0..8191 (s*K + k)
    const int s = i >> 10;
    const int k = i & 1023;
    const float* row = cb + (size_t)i * EDIM;
    float v[EDIM];
#pragma unroll
    for (int e = 0; e < EDIM; e++) v[e] = row[e];
    float c2 = 0.0f;
#pragma unroll
    for (int e = 0; e < EDIM; e++)
        c2 = __fadd_rn(c2, __fmul_rn(v[e], v[e]));
    g_cb2[i] = c2;
#pragma unroll
    for (int e2 = 0; e2 < EDIM/2; e2++)
        g_cbt[((size_t)s * (EDIM/2) + e2) * KCB + k] = packbf(v[2*e2], v[2*e2+1]);
}

struct Cand {
    int   cnt;
    int   pad[3];
    int   tok[CAP];
    int   kk[CAP];
    float dd[CAP];
};

// smem segment sizes (bytes)
#define SC_BYTES   (MTOK * SCP * 2)            // 132096
#define BS_BYTES   (2 * BUFW * 4)              // 34816 (double buffer)
#define RES_BYTES  (MTOK * RPITCH * 4)         // 17408
#define C2S_BYTES  (KCB * 4)                   // 4096 (full stage)
#define CAND_BYTES (NWARP * (int)sizeof(Cand)) // 9472
#define R2S_BYTES  (MTOK * 4)
#define TMIN_BYTES (MTOK * 4)
#define HIST_BYTES (NCODE * MTOK * 4)
#define SMEM_BYTES (SC_BYTES + BS_BYTES + RES_BYTES + C2S_BYTES + CAND_BYTES + \
                    R2S_BYTES + TMIN_BYTES + HIST_BYTES)

__global__ __launch_bounds__(TPB, 1)
void rvq_kernel(const float* __restrict__ emb,
                const float* __restrict__ cb,
                float* __restrict__ out)
{
    extern __shared__ char smem[];
    __half*   sc   = (__half*)smem;                        // [64][SCP]
    unsigned* bsw  = (unsigned*)(smem + SC_BYTES);         // 2 x [32][BPITCH]
    float*    res  = (float*)(smem + SC_BYTES + BS_BYTES); // [64][RPITCH]
    float*    c2s  = (float*)(smem + SC_BYTES + BS_BYTES + RES_BYTES); // [1024]
    Cand*     cands= (Cand*)(smem + SC_BYTES + BS_BYTES + RES_BYTES + C2S_BYTES);
    float*    r2s  = (float*)((char*)cands + CAND_BYTES);
    unsigned* tmin = (unsigned*)((char*)r2s + R2S_BYTES);  // [64] enc minima
    int*      hist = (int*)((char*)tmin + TMIN_BYTES);     // [s][tok]

    const int tid  = threadIdx.x;
    const int w    = tid >> 5;      // 0..15
    const int lane = tid & 31;
    const int qr   = lane >> 2;     // 0..7
    const int qc   = lane & 3;      // 0..3
    const int nw   = w & 7;         // n-slice (16 wide within gtile)
    const int mh   = w >> 3;        // m-half: m-tiles {2mh, 2mh+1}

    // B-gtile cooperative-load indices (2 uint4 per thread per gtile)
    const int ld_e2 = tid >> 5;          // 0..15 for j=0; +16 for j=1
    const int ld_c4 = tid & 31;          // 0..31 (uint4 within 128-k row)

    // ---- init: load embeddings into res smem ----
    {
        const int tok = tid & 63;
        const int ec  = tid >> 6;       // 0..7
        const int n   = blockIdx.x * MTOK + tok;
        const int b   = n >> 12;
        const int hw  = n & 4095;
        const float* ep = emb + (size_t)b * (EDIM * 4096) + hw;
#pragma unroll
        for (int j = 0; j < 8; j++) {
            int e = ec * 8 + j;
            res[tok * RPITCH + e] = ep[(size_t)e * 4096];
        }
    }
    __syncthreads();

#pragma unroll 1
    for (int s = 0; s < NCODE; s++) {
        const unsigned* gbase = g_cbt + (size_t)s * (EDIM/2) * KCB;

        // ---- per-stage init: tmin sentinel ----
        if (tid < MTOK) tmin[tid] = 0xFFFFFFFFu;

        // ---- A fragments: this warp's 2 m-tiles, bf16 packed (32 regs) ----
        unsigned a[2][16];
#pragma unroll
        for (int mtl = 0; mtl < 2; mtl++) {
            int r0 = (mh * 2 + mtl) * 16 + qr;
            const float* p0 = res + (size_t)r0 * RPITCH;
            const float* p1 = p0 + 8 * RPITCH;
#pragma unroll
            for (int ks = 0; ks < 4; ks++) {
                int c = 16 * ks + 2 * qc;
                a[mtl][ks*4+0] = packbf(p0[c],   p0[c+1]);
                a[mtl][ks*4+1] = packbf(p1[c],   p1[c+1]);
                a[mtl][ks*4+2] = packbf(p0[c+8], p0[c+9]);
                a[mtl][ks*4+3] = packbf(p1[c+8], p1[c+9]);
            }
        }
        // ---- exact r2 per token (sequential, e ascending) ----
        if (tid < MTOK) {
            const float* rr = res + tid * RPITCH;
            float r2 = 0.0f;
#pragma unroll
            for (int e = 0; e < EDIM; e++)
                r2 = __fadd_rn(r2, __fmul_rn(rr[e], rr[e]));
            r2s[tid] = r2;
        }

        // ---- prologue: c2s for whole stage + prefetch gtile 0 ----
        {
            c2s[tid]       = __ldg(g_cb2 + s * KCB + tid);
            c2s[tid + TPB] = __ldg(g_cb2 + s * KCB + tid + TPB);
            uint4 v0 = __ldg((const uint4*)(gbase + (size_t)(ld_e2     ) * KCB) + ld_c4);
            uint4 v1 = __ldg((const uint4*)(gbase + (size_t)(ld_e2 + 16) * KCB) + ld_c4);
            *(uint4*)(bsw + (ld_e2     ) * BPITCH + ld_c4 * 4) = v0;
            *(uint4*)(bsw + (ld_e2 + 16) * BPITCH + ld_c4 * 4) = v1;
        }
        __syncthreads();

        // running fp16 minima over this lane's stored scores
        const __half2 HMAX = __halves2half2(__half(65504.f), __half(65504.f));
        __half2 rmin[2][2] = { {HMAX, HMAX}, {HMAX, HMAX} };  // [mtl][row0/row1]

        // ---- score pass over K: 8 gtiles of 128, double-buffered ----
#pragma unroll 1
        for (int gt = 0; gt < NGT; gt++) {
            const unsigned* buf = bsw + (gt & 1) * BUFW;
            uint4 p0, p1;
            if (gt < NGT - 1) {
                const unsigned* gsrc = gbase + (gt + 1) * GTW;
                p0 = __ldg((const uint4*)(gsrc + (size_t)(ld_e2     ) * KCB) + ld_c4);
                p1 = __ldg((const uint4*)(gsrc + (size_t)(ld_e2 + 16) * KCB) + ld_c4);
            }

            const int n0 = nw * 16;
            {
                float acc[2][8];
#pragma unroll
                for (int mtl = 0; mtl < 2; mtl++)
#pragma unroll
                    for (int j = 0; j < 8; j++) acc[mtl][j] = 0.0f;

                const unsigned* bp = buf + n0 + qr;
#pragma unroll
                for (int ks = 0; ks < 4; ks++) {
                    unsigned b00 = bp[(ks*8     + qc) * BPITCH];
                    unsigned b01 = bp[(ks*8 + 4 + qc) * BPITCH];
                    unsigned b10 = bp[(ks*8     + qc) * BPITCH + 8];
                    unsigned b11 = bp[(ks*8 + 4 + qc) * BPITCH + 8];
#pragma unroll
                    for (int mtl = 0; mtl < 2; mtl++) {
                        mma_bf16(acc[mtl][0], acc[mtl][1], acc[mtl][2], acc[mtl][3],
                                 a[mtl][ks*4], a[mtl][ks*4+1], a[mtl][ks*4+2], a[mtl][ks*4+3],
                                 b00, b01);
                        mma_bf16(acc[mtl][4], acc[mtl][5], acc[mtl][6], acc[mtl][7],
                                 a[mtl][ks*4], a[mtl][ks*4+1], a[mtl][ks*4+2], a[mtl][ks*4+3],
                                 b10, b11);
                    }
                }
                // epilogue: t = cb2 - 2*dot -> fp16 scores + running minima
                const int gk  = gt * GTW;
                const int cc0 = gk + n0 + 2*qc;
                const int cc1 = cc0 + 8;
                float2 z0 = *(const float2*)(c2s + cc0);
                float2 z1 = *(const float2*)(c2s + cc1);
#pragma unroll
                for (int mtl = 0; mtl < 2; mtl++) {
                    int row0 = (mh * 2 + mtl) * 16 + qr, row1 = row0 + 8;
                    __half2 h00 = __halves2half2(__float2half_rn(fmaf(-2.f, acc[mtl][0], z0.x)),
                                                 __float2half_rn(fmaf(-2.f, acc[mtl][1], z0.y)));
                    __half2 h01 = __halves2half2(__float2half_rn(fmaf(-2.f, acc[mtl][2], z0.x)),
                                                 __float2half_rn(fmaf(-2.f, acc[mtl][3], z0.y)));
                    __half2 h10 = __halves2half2(__float2half_rn(fmaf(-2.f, acc[mtl][4], z1.x)),
                                                 __float2half_rn(fmaf(-2.f, acc[mtl][5], z1.y)));
                    __half2 h11 = __halves2half2(__float2half_rn(fmaf(-2.f, acc[mtl][6], z1.x)),
                                                 __float2half_rn(fmaf(-2.f, acc[mtl][7], z1.y)));
                    rmin[mtl][0] = __hmin2(rmin[mtl][0], __hmin2(h00, h10)); // row0
                    rmin[mtl][1] = __hmin2(rmin[mtl][1], __hmin2(h01, h11)); // row1
                    *(__half2*)(sc + row0 * SCP + cc0) = h00;
                    *(__half2*)(sc + row1 * SCP + cc0) = h01;
                    *(__half2*)(sc + row0 * SCP + cc1) = h10;
                    *(__half2*)(sc + row1 * SCP + cc1) = h11;
                }
            }

            if (gt < NGT - 1) {
                unsigned* nbuf = bsw + ((gt + 1) & 1) * BUFW;
                *(uint4*)(nbuf + (ld_e2     ) * BPITCH + ld_c4 * 4) = p0;
                *(uint4*)(nbuf + (ld_e2 + 16) * BPITCH + ld_c4 * 4) = p1;
            }
            __syncthreads();
        }

        // ---- fold lane minima -> tmin[token] via quad shfl + atomicMin ----
        {
#pragma unroll
            for (int mtl = 0; mtl < 2; mtl++) {
#pragma unroll
                for (int r = 0; r < 2; r++) {
                    __half2 h = rmin[mtl][r];
                    float f = __half2float(__hmin(__low2half(h), __high2half(h)));
                    f = fminf(f, __shfl_xor_sync(0xffffffffu, f, 1));
                    f = fminf(f, __shfl_xor_sync(0xffffffffu, f, 2));
                    if (qc == 0) {
                        int row = (mh * 2 + mtl) * 16 + qr + r * 8;
                        atomicMin(&tmin[row], fenc(f));
                    }
                }
            }
        }
        __syncthreads();   // scores + tmin complete

        // ---- per-warp candidate extraction: tokens w*4 .. w*4+3 ----
        Cand* cd = cands + w;
        if (lane == 0) cd->cnt = 0;
        __syncwarp();
        const int tbase = w * 4;
#pragma unroll 1
        for (int t4 = 0; t4 < 4; t4++) {
            const float thr = fdec(tmin[tbase + t4]) + MARGIN;
            const char* srow = (const char*)(sc + (tbase + t4) * SCP);
#pragma unroll
            for (int jj = 0; jj < 4; jj++) {
                uint4 v = *(const uint4*)(srow + jj*512 + lane*16);
                __half2 m0 = __hmin2(u2h2(v.x), u2h2(v.y));
                __half2 m1 = __hmin2(u2h2(v.z), u2h2(v.w));
                __half2 bm2 = __hmin2(m0, m1);
                float bm = __half2float(__hmin(__low2half(bm2), __high2half(bm2)));
                if (bm <= thr) {           // rare: fine-scan this 8-wide block
                    int kb = jj*256 + lane*8;
                    unsigned uu[4] = {v.x, v.y, v.z, v.w};
#pragma unroll
                    for (int mm = 0; mm < 4; mm++) {
                        __half2 h = u2h2(uu[mm]);
                        if (__half2float(__low2half(h)) <= thr) {
                            int p = atomicAdd(&cd->cnt, 1);
                            if (p < CAP) { cd->tok[p] = t4; cd->kk[p] = kb + 2*mm; }
                        }
                        if (__half2float(__high2half(h)) <= thr) {
                            int p = atomicAdd(&cd->cnt, 1);
                            if (p < CAP) { cd->tok[p] = t4; cd->kk[p] = kb + 2*mm + 1; }
                        }
                    }
                }
            }
        }
        __syncwarp();
        int ncand = min(cd->cnt, CAP);
        // parallel exact evaluation of all candidates (reference numerics)
        for (int base = 0; base < ncand; base += 32) {
            int i = base + lane;
            if (i < ncand) {
                int t4 = cd->tok[i];
                int k  = cd->kk[i];
                int tok = tbase + t4;
                const float4* q4 = (const float4*)(cb + ((size_t)(s * KCB + k)) * EDIM);
                const float* rr = res + tok * RPITCH;
                float dot = 0.0f;
#pragma unroll
                for (int ii = 0; ii < 16; ii++) {
                    float4 q = __ldg(q4 + ii);
                    dot = __fmaf_rn(rr[4*ii+0], q.x, dot);
                    dot = __fmaf_rn(rr[4*ii+1], q.y, dot);
                    dot = __fmaf_rn(rr[4*ii+2], q.z, dot);
                    dot = __fmaf_rn(rr[4*ii+3], q.w, dot);
                }
                cd->dd[i] = __fadd_rn(__fsub_rn(r2s[tok], __fmul_rn(2.0f, dot)),
                                      c2s[k]);
            }
        }
        __syncwarp();
        // per-token select with first-index tie-break (lanes 0..3)
        int bk = KCB;
        if (lane < 4) {
            float bd = FLT_MAX;
            for (int i = 0; i < ncand; i++) {
                if (cd->tok[i] == lane) {
                    float d = cd->dd[i]; int k = cd->kk[i];
                    if (d < bd || (d == bd && k < bk)) { bd = d; bk = k; }
                }
            }
            hist[s * MTOK + tbase + lane] = bk;
        }
        __syncwarp();

        // ---- residual update (exact), warp-local via shfl broadcast ----
        {
            int t4   = lane >> 3;          // local token 0..3
            int part = lane & 7;           // 8 floats each
            int k    = __shfl_sync(0xffffffffu, bk, t4);
            int tok  = tbase + t4;
            const float4* qp = (const float4*)(cb + ((size_t)(s * KCB + k)) * EDIM) + part * 2;
            float* rr = res + tok * RPITCH + part * 8;
#pragma unroll
            for (int ii = 0; ii < 2; ii++) {
                float4 q  = __ldg(qp + ii);
                float4 rv = *(float4*)(rr + 4*ii);
                rv.x = __fsub_rn(rv.x, q.x);
                rv.y = __fsub_rn(rv.y, q.y);
                rv.z = __fsub_rn(rv.z, q.z);
                rv.w = __fsub_rn(rv.w, q.w);
                *(float4*)(rr + 4*ii) = rv;
            }
        }
        __syncthreads();   // res updates visible to all warps (next A-frags)
    }

    // ---- final epilogue: quant = ((q0+q1)+q2)...+q7, exact order ----
    {
        const int tok = tid & 63;
        const int ec  = tid >> 6;          // 0..7
        const int e0  = ec * 8;
        const int n   = blockIdx.x * MTOK + tok;
        const int b   = n >> 12;
        const int hw  = n & 4095;

        float4 acc[2];
        {
            int k = hist[0 * MTOK + tok];
            const float4* qp = (const float4*)(cb + ((size_t)(0 * KCB + k)) * EDIM + e0);
#pragma unroll
            for (int ii = 0; ii < 2; ii++) acc[ii] = __ldg(qp + ii);
        }
#pragma unroll
        for (int s = 1; s < NCODE; s++) {
            int k = hist[s * MTOK + tok];
            const float4* qp = (const float4*)(cb + ((size_t)(s * KCB + k)) * EDIM + e0);
#pragma unroll
            for (int ii = 0; ii < 2; ii++) {
                float4 q = __ldg(qp + ii);
                acc[ii].x = __fadd_rn(acc[ii].x, q.x);
                acc[ii].y = __fadd_rn(acc[ii].y, q.y);
                acc[ii].z = __fadd_rn(acc[ii].z, q.z);
                acc[ii].w = __fadd_rn(acc[ii].w, q.w);
            }
        }
        float* op = out + (size_t)b * (EDIM * 4096) + hw;
#pragma unroll
        for (int ii = 0; ii < 2; ii++) {
            op[(size_t)(e0 + 4*ii + 0) * 4096] = acc[ii].x;
            op[(size_t)(e0 + 4*ii + 1) * 4096] = acc[ii].y;
            op[(size_t)(e0 + 4*ii + 2) * 4096] = acc[ii].z;
            op[(size_t)(e0 + 4*ii + 3) * 4096] = acc[ii].w;
        }
    }
}

extern "C" void kernel_launch(void* const* d_in, const int* in_sizes, int n_in,
                              void* d_out, int out_size)
{
    const float* emb = (const float*)d_in[0];   // [16,64,64,64]
    const float* cb  = (const float*)d_in[1];   // [8,1024,64]
    float* out = (float*)d_out;
    (void)in_sizes; (void)n_in; (void)out_size;

    cudaFuncSetAttribute(rvq_kernel, cudaFuncAttributeMaxDynamicSharedMemorySize,
                         SMEM_BYTES);

    prep_kernel<<<(NCODE * KCB) / 256, 256>>>(cb);
    rvq_kernel<<<NTOK / MTOK, TPB, SMEM_BYTES>>>(emb, cb, out);
}

// round 16
// speedup vs baseline: 1.0008x; 1.0008x over previous
#include <cuda_runtime.h>
#include <cuda_fp16.h>
#include <cuda_bf16.h>
#include <cfloat>
#include <cstdint>

// ResidualVectorQuantizer, exact argmin via bf16-MMA prefilter + scalar verify.
// B=16,E=64,H=64,W=64 -> N=65536 tokens; K=1024, NC=8 stages.
//
// Exact reference numerics (validated rel_err==0 in rounds 1-6, 8, 10, 13):
//   r2  = sequential sum of rounded squares of res (e ascending)
//   dot = sequential fused-FMA over e ascending
//   d   = fl(fl(r2 - fl(2*dot)) + cb2), argmin first-index tie-break
//   res -= q elementwise rounded; quant = ((q0+q1)+...)+q7
// MMA computes approximate scores t~ = cb2 - 2*dot~ (bf16 in, f32 acc,
// fp16-stored); every k with t~ <= min + MARGIN=2e-3 is re-verified exactly.
//
// R14 = R13 (716us best, profiled: L1 57%, no pipe saturated) + 3 edits:
//  1. per-token score min tracked in registers during the MMA epilogue
//     (hmin2 of the exact same fp16 values that get stored) + quad-shfl +
//     atomicMin(float-ordered uint) -> identical thr, identical candidates
//  2. scan drops its min pass entirely (pure threshold extraction)
//  3. select/residual-update are warp-local: post-select barrier -> shfl
//     broadcast of k; sel[] removed

#define NTOK   65536
#define EDIM   64
#define KCB    1024
#define NCODE  8
#define MTOK   64          // tokens per CTA
#define TPB    512
#define NWARP  16
#define GTW    128         // codebook k-gtile width (codewords)
#define NGT    (KCB / GTW) // 8 gtiles
#define BPITCH 136         // B tile pitch in 32-bit words (136%32==8)
#define BUFW   (32 * BPITCH)   // words per B buffer
#define RPITCH 68          // res row pitch (floats)
#define SCP    1032        // score row pitch (halves)
#define CAP    48
#define MARGIN 2e-3f

// packed bf16 pairs along e: word(e2,k) = {lo=cb[k][2e2], hi=cb[k][2e2+1]}
__device__ unsigned g_cbt[NCODE * (EDIM/2) * KCB];
__device__ float    g_cb2[NCODE * KCB];         // exact ||cb||^2

__device__ __forceinline__ unsigned packbf(float lo, float hi) {
    unsigned r;
    asm("cvt.rn.bf16x2.f32 %0, %1, %2;" : "=r"(r) : "f"(hi), "f"(lo));
    return r;
}

__device__ __forceinline__ __half2 u2h2(unsigned u) {
    return *reinterpret_cast<__half2*>(&u);
}

// float <-> order-preserving unsigned (for atomicMin on floats, no NaNs)
__device__ __forceinline__ unsigned fenc(float f) {
    unsigned u = __float_as_uint(f);
    return (u & 0x80000000u) ? ~u : (u | 0x80000000u);
}
__device__ __forceinline__ float fdec(unsigned e) {
    return (e & 0x80000000u) ? __uint_as_float(e ^ 0x80000000u)
                             : __uint_as_float(~e);
}

__device__ __forceinline__ void mma_bf16(float& c0, float& c1, float& c2, float& c3,
                                         unsigned a0, unsigned a1, unsigned a2, unsigned a3,
                                         unsigned b0, unsigned b1) {
    asm volatile(
        "mma.sync.aligned.m16n8k16.row.col.f32.bf16.bf16.f32 "
        "{%0,%1,%2,%3}, {%4,%5,%6,%7}, {%8,%9}, {%0,%1,%2,%3};\n"
        : "+f"(c0), "+f"(c1), "+f"(c2), "+f"(c3)
        : "r"(a0), "r"(a1), "r"(a2), "r"(a3), "r"(b0), "r"(b1));
}

// ---- precompute: exact cb2 + transposed bf16-packed codebook ----
__global__ void prep_kernel(const float* __restrict__ cb)
{
    const int i = blockIdx.x * blockDim.x + threadIdx.x;   // 0..8191 (s*K + k)
    const int s = i >> 10;
    const int k = i & 1023;
    const float* row = cb + (size_t)i * EDIM;
    float v[EDIM];
#pragma unroll
    for (int e = 0; e < EDIM; e++) v[e] = row[e];
    float c2 = 0.0f;
#pragma unroll
    for (int e = 0; e < EDIM; e++)
        c2 = __fadd_rn(c2, __fmul_rn(v[e], v[e]));
    g_cb2[i] = c2;
#pragma unroll
    for (int e2 = 0; e2 < EDIM/2; e2++)
        g_cbt[((size_t)s * (EDIM/2) + e2) * KCB + k] = packbf(v[2*e2], v[2*e2+1]);
}

struct Cand {
    int   cnt;
    int   pad[3];
    int   tok[CAP];
    int   kk[CAP];
    float dd[CAP];
};

// smem segment sizes (bytes)
#define SC_BYTES   (MTOK * SCP * 2)            // 132096
#define BS_BYTES   (2 * BUFW * 4)              // 34816 (double buffer)
#define RES_BYTES  (MTOK * RPITCH * 4)         // 17408
#define C2S_BYTES  (KCB * 4)                   // 4096 (full stage)
#define CAND_BYTES (NWARP * (int)sizeof(Cand)) // 9472
#define R2S_BYTES  (MTOK * 4)
#define TMIN_BYTES (MTOK * 4)
#define HIST_BYTES (NCODE * MTOK * 4)
#define SMEM_BYTES (SC_BYTES + BS_BYTES + RES_BYTES + C2S_BYTES + CAND_BYTES + \
                    R2S_BYTES + TMIN_BYTES + HIST_BYTES)

__global__ __launch_bounds__(TPB, 1)
void rvq_kernel(const float* __restrict__ emb,
                const float* __restrict__ cb,
                float* __restrict__ out)
{
    extern __shared__ char smem[];
    __half*   sc   = (__half*)smem;                        // [64][SCP]
    unsigned* bsw  = (unsigned*)(smem + SC_BYTES);         // 2 x [32][BPITCH]
    float*    res  = (float*)(smem + SC_BYTES + BS_BYTES); // [64][RPITCH]
    float*    c2s  = (float*)(smem + SC_BYTES + BS_BYTES + RES_BYTES); // [1024]
    Cand*     cands= (Cand*)(smem + SC_BYTES + BS_BYTES + RES_BYTES + C2S_BYTES);
    float*    r2s  = (float*)((char*)cands + CAND_BYTES);
    unsigned* tmin = (unsigned*)((char*)r2s + R2S_BYTES);  // [64] enc minima
    int*      hist = (int*)((char*)tmin + TMIN_BYTES);     // [s][tok]

    const int tid  = threadIdx.x;
    const int w    = tid >> 5;      // 0..15
    const int lane = tid & 31;
    const int qr   = lane >> 2;     // 0..7
    const int qc   = lane & 3;      // 0..3
    const int nw   = w & 7;         // n-slice (16 wide within gtile)
    const int mh   = w >> 3;        // m-half: m-tiles {2mh, 2mh+1}

    // B-gtile cooperative-load indices (2 uint4 per thread per gtile)
    const int ld_e2 = tid >> 5;          // 0..15 for j=0; +16 for j=1
    const int ld_c4 = tid & 31;          // 0..31 (uint4 within 128-k row)

    // ---- init: load embeddings into res smem ----
    {
        const int tok = tid & 63;
        const int ec  = tid >> 6;       // 0..7
        const int n   = blockIdx.x * MTOK + tok;
        const int b   = n >> 12;
        const int hw  = n & 4095;
        const float* ep = emb + (size_t)b * (EDIM * 4096) + hw;
#pragma unroll
        for (int j = 0; j < 8; j++) {
            int e = ec * 8 + j;
            res[tok * RPITCH + e] = ep[(size_t)e * 4096];
        }
    }
    __syncthreads();

#pragma unroll 1
    for (int s = 0; s < NCODE; s++) {
        const unsigned* gbase = g_cbt + (size_t)s * (EDIM/2) * KCB;

        // ---- per-stage init: tmin sentinel ----
        if (tid < MTOK) tmin[tid] = 0xFFFFFFFFu;

        // ---- A fragments: this warp's 2 m-tiles, bf16 packed (32 regs) ----
        unsigned a[2][16];
#pragma unroll
        for (int mtl = 0; mtl < 2; mtl++) {
            int r0 = (mh * 2 + mtl) * 16 + qr;
            const float* p0 = res + (size_t)r0 * RPITCH;
            const float* p1 = p0 + 8 * RPITCH;
#pragma unroll
            for (int ks = 0; ks < 4; ks++) {
                int c = 16 * ks + 2 * qc;
                a[mtl][ks*4+0] = packbf(p0[c],   p0[c+1]);
                a[mtl][ks*4+1] = packbf(p1[c],   p1[c+1]);
                a[mtl][ks*4+2] = packbf(p0[c+8], p0[c+9]);
                a[mtl][ks*4+3] = packbf(p1[c+8], p1[c+9]);
            }
        }
        // ---- exact r2 per token (sequential, e ascending) ----
        if (tid < MTOK) {
            const float* rr = res + tid * RPITCH;
            float r2 = 0.0f;
#pragma unroll
            for (int e = 0; e < EDIM; e++)
                r2 = __fadd_rn(r2, __fmul_rn(rr[e], rr[e]));
            r2s[tid] = r2;
        }

        // ---- prologue: c2s for whole stage + prefetch gtile 0 ----
        {
            c2s[tid]       = __ldg(g_cb2 + s * KCB + tid);
            c2s[tid + TPB] = __ldg(g_cb2 + s * KCB + tid + TPB);
            uint4 v0 = __ldg((const uint4*)(gbase + (size_t)(ld_e2     ) * KCB) + ld_c4);
            uint4 v1 = __ldg((const uint4*)(gbase + (size_t)(ld_e2 + 16) * KCB) + ld_c4);
            *(uint4*)(bsw + (ld_e2     ) * BPITCH + ld_c4 * 4) = v0;
            *(uint4*)(bsw + (ld_e2 + 16) * BPITCH + ld_c4 * 4) = v1;
        }
        __syncthreads();

        // running fp16 minima over this lane's stored scores
        const __half2 HMAX = __halves2half2(__half(65504.f), __half(65504.f));
        __half2 rmin[2][2] = { {HMAX, HMAX}, {HMAX, HMAX} };  // [mtl][row0/row1]

        // ---- score pass over K: 8 gtiles of 128, double-buffered ----
#pragma unroll 1
        for (int gt = 0; gt < NGT; gt++) {
            const unsigned* buf = bsw + (gt & 1) * BUFW;
            uint4 p0, p1;
            if (gt < NGT - 1) {
                const unsigned* gsrc = gbase + (gt + 1) * GTW;
                p0 = __ldg((const uint4*)(gsrc + (size_t)(ld_e2     ) * KCB) + ld_c4);
                p1 = __ldg((const uint4*)(gsrc + (size_t)(ld_e2 + 16) * KCB) + ld_c4);
            }

            const int n0 = nw * 16;
            {
                float acc[2][8];
#pragma unroll
                for (int mtl = 0; mtl < 2; mtl++)
#pragma unroll
                    for (int j = 0; j < 8; j++) acc[mtl][j] = 0.0f;

                const unsigned* bp = buf + n0 + qr;
#pragma unroll
                for (int ks = 0; ks < 4; ks++) {
                    unsigned b00 = bp[(ks*8     + qc) * BPITCH];
                    unsigned b01 = bp[(ks*8 + 4 + qc) * BPITCH];
                    unsigned b10 = bp[(ks*8     + qc) * BPITCH + 8];
                    unsigned b11 = bp[(ks*8 + 4 + qc) * BPITCH + 8];
#pragma unroll
                    for (int mtl = 0; mtl < 2; mtl++) {
                        mma_bf16(acc[mtl][0], acc[mtl][1], acc[mtl][2], acc[mtl][3],
                                 a[mtl][ks*4], a[mtl][ks*4+1], a[mtl][ks*4+2], a[mtl][ks*4+3],
                                 b00, b01);
                        mma_bf16(acc[mtl][4], acc[mtl][5], acc[mtl][6], acc[mtl][7],
                                 a[mtl][ks*4], a[mtl][ks*4+1], a[mtl][ks*4+2], a[mtl][ks*4+3],
                                 b10, b11);
                    }
                }
                // epilogue: t = cb2 - 2*dot -> fp16 scores + running minima
                const int gk  = gt * GTW;
                const int cc0 = gk + n0 + 2*qc;
                const int cc1 = cc0 + 8;
                float2 z0 = *(const float2*)(c2s + cc0);
                float2 z1 = *(const float2*)(c2s + cc1);
#pragma unroll
                for (int mtl = 0; mtl < 2; mtl++) {
                    int row0 = (mh * 2 + mtl) * 16 + qr, row1 = row0 + 8;
                    __half2 h00 = __halves2half2(__float2half_rn(fmaf(-2.f, acc[mtl][0], z0.x)),
                                                 __float2half_rn(fmaf(-2.f, acc[mtl][1], z0.y)));
                    __half2 h01 = __halves2half2(__float2half_rn(fmaf(-2.f, acc[mtl][2], z0.x)),
                                                 __float2half_rn(fmaf(-2.f, acc[mtl][3], z0.y)));
                    __half2 h10 = __halves2half2(__float2half_rn(fmaf(-2.f, acc[mtl][4], z1.x)),
                                                 __float2half_rn(fmaf(-2.f, acc[mtl][5], z1.y)));
                    __half2 h11 = __halves2half2(__float2half_rn(fmaf(-2.f, acc[mtl][6], z1.x)),
                                                 __float2half_rn(fmaf(-2.f, acc[mtl][7], z1.y)));
                    rmin[mtl][0] = __hmin2(rmin[mtl][0], __hmin2(h00, h10)); // row0
                    rmin[mtl][1] = __hmin2(rmin[mtl][1], __hmin2(h01, h11)); // row1
                    *(__half2*)(sc + row0 * SCP + cc0) = h00;
                    *(__half2*)(sc + row1 * SCP + cc0) = h01;
                    *(__half2*)(sc + row0 * SCP + cc1) = h10;
                    *(__half2*)(sc + row1 * SCP + cc1) = h11;
                }
            }

            if (gt < NGT - 1) {
                unsigned* nbuf = bsw + ((gt + 1) & 1) * BUFW;
                *(uint4*)(nbuf + (ld_e2     ) * BPITCH + ld_c4 * 4) = p0;
                *(uint4*)(nbuf + (ld_e2 + 16) * BPITCH + ld_c4 * 4) = p1;
            }
            __syncthreads();
        }

        // ---- fold lane minima -> tmin[token] via quad shfl + atomicMin ----
        {
#pragma unroll
            for (int mtl = 0; mtl < 2; mtl++) {
#pragma unroll
                for (int r = 0; r < 2; r++) {
                    __half2 h = rmin[mtl][r];
                    float f = __half2float(__hmin(__low2half(h), __high2half(h)));
                    f = fminf(f, __shfl_xor_sync(0xffffffffu, f, 1));
                    f = fminf(f, __shfl_xor_sync(0xffffffffu, f, 2));
                    if (qc == 0) {
                        int row = (mh * 2 + mtl) * 16 + qr + r * 8;
                        atomicMin(&tmin[row], fenc(f));
                    }
                }
            }
        }
        __syncthreads();   // scores + tmin complete

        // ---- per-warp candidate extraction: tokens w*4 .. w*4+3 ----
        Cand* cd = cands + w;
        if (lane == 0) cd->cnt = 0;
        __syncwarp();
        const int tbase = w * 4;
#pragma unroll 1
        for (int t4 = 0; t4 < 4; t4++) {
            const float thr = fdec(tmin[tbase + t4]) + MARGIN;
            const char* srow = (const char*)(sc + (tbase + t4) * SCP);
#pragma unroll
            for (int jj = 0; jj < 4; jj++) {
                uint4 v = *(const uint4*)(srow + jj*512 + lane*16);
                __half2 m0 = __hmin2(u2h2(v.x), u2h2(v.y));
                __half2 m1 = __hmin2(u2h2(v.z), u2h2(v.w));
                __half2 bm2 = __hmin2(m0, m1);
                float bm = __half2float(__hmin(__low2half(bm2), __high2half(bm2)));
                if (bm <= thr) {           // rare: fine-scan this 8-wide block
                    int kb = jj*256 + lane*8;
                    unsigned uu[4] = {v.x, v.y, v.z, v.w};
#pragma unroll
                    for (int mm = 0; mm < 4; mm++) {
                        __half2 h = u2h2(uu[mm]);
                        if (__half2float(__low2half(h)) <= thr) {
                            int p = atomicAdd(&cd->cnt, 1);
                            if (p < CAP) { cd->tok[p] = t4; cd->kk[p] = kb + 2*mm; }
                        }
                        if (__half2float(__high2half(h)) <= thr) {
                            int p = atomicAdd(&cd->cnt, 1);
                            if (p < CAP) { cd->tok[p] = t4; cd->kk[p] = kb + 2*mm + 1; }
                        }
                    }
                }
            }
        }
        __syncwarp();
        int ncand = min(cd->cnt, CAP);
        // parallel exact evaluation of all candidates (reference numerics)
        for (int base = 0; base < ncand; base += 32) {
            int i = base + lane;
            if (i < ncand) {
                int t4 = cd->tok[i];
                int k  = cd->kk[i];
                int tok = tbase + t4;
                const float4* q4 = (const float4*)(cb + ((size_t)(s * KCB + k)) * EDIM);
                const float* rr = res + tok * RPITCH;
                float dot = 0.0f;
#pragma unroll
                for (int ii = 0; ii < 16; ii++) {
                    float4 q = __ldg(q4 + ii);
                    dot = __fmaf_rn(rr[4*ii+0], q.x, dot);
                    dot = __fmaf_rn(rr[4*ii+1], q.y, dot);
                    dot = __fmaf_rn(rr[4*ii+2], q.z, dot);
                    dot = __fmaf_rn(rr[4*ii+3], q.w, dot);
                }
                cd->dd[i] = __fadd_rn(__fsub_rn(r2s[tok], __fmul_rn(2.0f, dot)),
                                      c2s[k]);
            }
        }
        __syncwarp();
        // per-token select with first-index tie-break (lanes 0..3)
        int bk = KCB;
        if (lane < 4) {
            float bd = FLT_MAX;
            for (int i = 0; i < ncand; i++) {
                if (cd->tok[i] == lane) {
                    float d = cd->dd[i]; int k = cd->kk[i];
                    if (d < bd || (d == bd && k < bk)) { bd = d; bk = k; }
                }
            }
            hist[s * MTOK + tbase + lane] = bk;
        }
        __syncwarp();

        // ---- residual update (exact), warp-local via shfl broadcast ----
        {
            int t4   = lane >> 3;          // local token 0..3
            int part = lane & 7;           // 8 floats each
            int k    = __shfl_sync(0xffffffffu, bk, t4);
            int tok  = tbase + t4;
            const float4* qp = (const float4*)(cb + ((size_t)(s * KCB + k)) * EDIM) + part * 2;
            float* rr = res + tok * RPITCH + part * 8;
#pragma unroll
            for (int ii = 0; ii < 2; ii++) {
                float4 q  = __ldg(qp + ii);
                float4 rv = *(float4*)(rr + 4*ii);
                rv.x = __fsub_rn(rv.x, q.x);
                rv.y = __fsub_rn(rv.y, q.y);
                rv.z = __fsub_rn(rv.z, q.z);
                rv.w = __fsub_rn(rv.w, q.w);
                *(float4*)(rr + 4*ii) = rv;
            }
        }
        __syncthreads();   // res updates visible to all warps (next A-frags)
    }

    // ---- final epilogue: quant = ((q0+q1)+q2)...+q7, exact order ----
    {
        const int tok = tid & 63;
        const int ec  = tid >> 6;          // 0..7
        const int e0  = ec * 8;
        const int n   = blockIdx.x * MTOK + tok;
        const int b   = n >> 12;
        const int hw  = n & 4095;

        float4 acc[2];
        {
            int k = hist[0 * MTOK + tok];
            const float4* qp = (const float4*)(cb + ((size_t)(0 * KCB + k)) * EDIM + e0);
#pragma unroll
            for (int ii = 0; ii < 2; ii++) acc[ii] = __ldg(qp + ii);
        }
#pragma unroll
        for (int s = 1; s < NCODE; s++) {
            int k = hist[s * MTOK + tok];
            const float4* qp = (const float4*)(cb + ((size_t)(s * KCB + k)) * EDIM + e0);
#pragma unroll
            for (int ii = 0; ii < 2; ii++) {
                float4 q = __ldg(qp + ii);
                acc[ii].x = __fadd_rn(acc[ii].x, q.x);
                acc[ii].y = __fadd_rn(acc[ii].y, q.y);
                acc[ii].z = __fadd_rn(acc[ii].z, q.z);
                acc[ii].w = __fadd_rn(acc[ii].w, q.w);
            }
        }
        float* op = out + (size_t)b * (EDIM * 4096) + hw;
#pragma unroll
        for (int ii = 0; ii < 2; ii++) {
            op[(size_t)(e0 + 4*ii + 0) * 4096] = acc[ii].x;
            op[(size_t)(e0 + 4*ii + 1) * 4096] = acc[ii].y;
            op[(size_t)(e0 + 4*ii + 2) * 4096] = acc[ii].z;
            op[(size_t)(e0 + 4*ii + 3) * 4096] = acc[ii].w;
        }
    }
}

extern "C" void kernel_launch(void* const* d_in, const int* in_sizes, int n_in,
                              void* d_out, int out_size)
{
    const float* emb = (const float*)d_in[0];   // [16,64,64,64]
    const float* cb  = (const float*)d_in[1];   // [8,1024,64]
    float* out = (float*)d_out;
    (void)in_sizes; (void)n_in; (void)out_size;

    cudaFuncSetAttribute(rvq_kernel, cudaFuncAttributeMaxDynamicSharedMemorySize,
                         SMEM_BYTES);

    prep_kernel<<<(NCODE * KCB) / 256, 256>>>(cb);
    rvq_kernel<<<NTOK / MTOK, TPB, SMEM_BYTES>>>(emb, cb, out);
}